// round 5
// baseline (speedup 1.0000x reference)
#include <cuda_runtime.h>

// ---------------------------------------------------------------------------
// AbstractConv3D v3: v2 + latency hiding. One block per 8x8x8 tile, 128 thr,
// thread owns a z-quad of 4 voxels. Per tap: hoist all 16 input LDS.128 into
// registers (64 regs), fully unroll ci4 so ptxas pipelines weight-LDS/dup/FMA2.
// 16 output channels x 4 voxels as 32 packed f32x2 accumulators (fma.rn.f32x2).
// ---------------------------------------------------------------------------

#define N_TOTAL 1846083
#define N_TILES 4059      // sum over levels of ceil(R/8)^3
#define PAD     20        // floats per voxel in smem halo (16 data + 4 pad)

__constant__ int c_R[16]    = {16,18,20,22,25,27,30,34,38,42,47,52,58,64,72,80};
__constant__ int c_off[16]  = {0,4096,9928,17928,28576,44201,63884,90884,
                               130188,185060,259148,362971,503579,698691,960835,1334083};
__constant__ int c_Tdim[16] = {2,3,3,3,4,4,4,5,5,6,6,7,8,8,9,10};
__constant__ int c_tcum[16] = {8,35,62,89,153,217,281,406,531,747,963,1306,1818,2330,3059,4059};

__device__ __forceinline__ unsigned long long ffma2(unsigned long long a,
                                                    unsigned long long b,
                                                    unsigned long long c) {
    unsigned long long d;
    asm("fma.rn.f32x2 %0, %1, %2, %3;" : "=l"(d) : "l"(a), "l"(b), "l"(c));
    return d;
}
__device__ __forceinline__ unsigned long long dup2(float x) {
    unsigned long long r;
    asm("mov.b64 %0, {%1, %1};" : "=l"(r) : "f"(x));
    return r;
}
__device__ __forceinline__ unsigned long long pack2(float lo, float hi) {
    unsigned long long r;
    asm("mov.b64 %0, {%1, %2};" : "=l"(r) : "f"(lo), "f"(hi));
    return r;
}

#define SMEM_IN_FLOATS (1000 * PAD)           // 20000 floats = 80 KB
#define SMEM_W_FLOATS  6912                   // 27*16*16     = 27.6 KB
#define SMEM_BYTES     ((SMEM_IN_FLOATS + SMEM_W_FLOATS) * 4)

__global__ void __launch_bounds__(128, 2)
conv3d_v3_kernel(const float* __restrict__ input,
                 const float* __restrict__ weight,
                 const float* __restrict__ bias,
                 float* __restrict__ out)
{
    extern __shared__ float smem[];
    float* s_in = smem;                       // [1000][PAD]
    float* s_w  = smem + SMEM_IN_FLOATS;      // [27][16][16]

    const int t   = blockIdx.x;
    const int b   = blockIdx.y;
    const int tid = threadIdx.x;

    // tile -> level
    int l = 0;
    while (t >= c_tcum[l]) ++l;
    const int base  = l ? c_tcum[l - 1] : 0;
    int local = t - base;
    const int T   = c_Tdim[l];
    const int R   = c_R[l];
    const int off = c_off[l];
    const int tx  = local % T;
    local /= T;
    const int ty  = local % T;
    const int tz  = local / T;
    const int x0 = tx * 8, y0 = ty * 8, z0 = tz * 8;

    // ---- load halo (zeros outside grid = SAME zero padding) ----
    const float* inbase = input + (size_t)b * N_TOTAL * 16;
    for (int h = tid; h < 1000; h += 128) {
        const int hx = h % 10;
        const int hq = h / 10;
        const int hy = hq % 10;
        const int hz = hq / 10;
        const int gx = x0 - 1 + hx;
        const int gy = y0 - 1 + hy;
        const int gz = z0 - 1 + hz;
        float* dst = &s_in[h * PAD];
        if ((unsigned)gx < (unsigned)R && (unsigned)gy < (unsigned)R &&
            (unsigned)gz < (unsigned)R) {
            const float4* src = (const float4*)(inbase +
                (size_t)(off + gx + gy * R + gz * R * R) * 16);
            ((float4*)dst)[0] = src[0];
            *(float4*)(dst + 4)  = src[1];
            *(float4*)(dst + 8)  = src[2];
            *(float4*)(dst + 12) = src[3];
        } else {
            const float4 z4 = make_float4(0.f, 0.f, 0.f, 0.f);
            ((float4*)dst)[0] = z4;
            *(float4*)(dst + 4)  = z4;
            *(float4*)(dst + 8)  = z4;
            *(float4*)(dst + 12) = z4;
        }
    }
    // ---- load weights for this level ----
    {
        const float4* wsrc = (const float4*)(weight + (size_t)l * SMEM_W_FLOATS);
        float4* wdst = (float4*)s_w;
        for (int i = tid; i < SMEM_W_FLOATS / 4; i += 128) wdst[i] = wsrc[i];
    }
    __syncthreads();

    // ---- compute: thread (x, y, zh) owns voxels z = 4*zh + {0,1,2,3} ----
    const int x  = tid & 7;
    const int y  = (tid >> 3) & 7;
    const int zh = tid >> 6;          // 0 or 1

    unsigned long long acc[4][8];
    {
        const float* bp = bias + l * 16;
        #pragma unroll
        for (int j = 0; j < 8; ++j) {
            const unsigned long long bj = pack2(bp[2 * j], bp[2 * j + 1]);
            acc[0][j] = bj; acc[1][j] = bj; acc[2][j] = bj; acc[3][j] = bj;
        }
    }

    const int hbase = ((4 * zh + 1) * 100 + (y + 1) * 10 + (x + 1)) * PAD;
    const int ZSTRIDE = 100 * PAD;

    #pragma unroll 1
    for (int tap = 0; tap < 27; ++tap) {
        const int dz  = tap / 9;
        const int rem = tap - dz * 9;
        const int dy  = rem / 3;
        const int dx  = rem - dy * 3;
        const int noff = ((dz - 1) * 100 + (dy - 1) * 10 + (dx - 1)) * PAD;

        const float* vb   = s_in + hbase + noff;
        const float* wtap = s_w + tap * 256;

        // hoist ALL input loads for this tap: 16 independent LDS.128
        float4 A[4][4];   // [ci4][voxel]
        #pragma unroll
        for (int ci4 = 0; ci4 < 4; ++ci4) {
            #pragma unroll
            for (int v = 0; v < 4; ++v) {
                A[ci4][v] = *(const float4*)(vb + v * ZSTRIDE + ci4 * 4);
            }
        }

        #pragma unroll
        for (int ci4 = 0; ci4 < 4; ++ci4) {
            const float av[4][4] = {
                {A[ci4][0].x, A[ci4][0].y, A[ci4][0].z, A[ci4][0].w},
                {A[ci4][1].x, A[ci4][1].y, A[ci4][1].z, A[ci4][1].w},
                {A[ci4][2].x, A[ci4][2].y, A[ci4][2].z, A[ci4][2].w},
                {A[ci4][3].x, A[ci4][3].y, A[ci4][3].z, A[ci4][3].w}};
            #pragma unroll
            for (int c = 0; c < 4; ++c) {
                const unsigned long long xd0 = dup2(av[0][c]);
                const unsigned long long xd1 = dup2(av[1][c]);
                const unsigned long long xd2 = dup2(av[2][c]);
                const unsigned long long xd3 = dup2(av[3][c]);
                const ulonglong2* wr = (const ulonglong2*)&wtap[(ci4 * 4 + c) * 16];
                #pragma unroll
                for (int q = 0; q < 4; ++q) {
                    const ulonglong2 w = wr[q];   // warp-uniform broadcast
                    acc[0][2 * q]     = ffma2(xd0, w.x, acc[0][2 * q]);
                    acc[0][2 * q + 1] = ffma2(xd0, w.y, acc[0][2 * q + 1]);
                    acc[1][2 * q]     = ffma2(xd1, w.x, acc[1][2 * q]);
                    acc[1][2 * q + 1] = ffma2(xd1, w.y, acc[1][2 * q + 1]);
                    acc[2][2 * q]     = ffma2(xd2, w.x, acc[2][2 * q]);
                    acc[2][2 * q + 1] = ffma2(xd2, w.y, acc[2][2 * q + 1]);
                    acc[3][2 * q]     = ffma2(xd3, w.x, acc[3][2 * q]);
                    acc[3][2 * q + 1] = ffma2(xd3, w.y, acc[3][2 * q + 1]);
                }
            }
        }
    }

    // ---- store 4 voxels (guarded against tile overhang) ----
    const int gx = x0 + x, gy = y0 + y;
    if (gx < R && gy < R) {
        float* outbase = out + (size_t)b * N_TOTAL * 16;
        const size_t xybase = (size_t)(off + gx + gy * R);
        #pragma unroll
        for (int k = 0; k < 4; ++k) {
            const int gz = z0 + 4 * zh + k;
            if (gz < R) {
                ulonglong2* o = (ulonglong2*)(outbase +
                    (xybase + (size_t)gz * R * R) * 16);
                o[0] = make_ulonglong2(acc[k][0], acc[k][1]);
                o[1] = make_ulonglong2(acc[k][2], acc[k][3]);
                o[2] = make_ulonglong2(acc[k][4], acc[k][5]);
                o[3] = make_ulonglong2(acc[k][6], acc[k][7]);
            }
        }
    }
}

extern "C" void kernel_launch(void* const* d_in, const int* in_sizes, int n_in,
                              void* d_out, int out_size)
{
    const float* input  = (const float*)d_in[0];
    const float* weight = (const float*)d_in[1];
    const float* bias   = (const float*)d_in[2];
    float* out = (float*)d_out;

    cudaFuncSetAttribute(conv3d_v3_kernel,
                         cudaFuncAttributeMaxDynamicSharedMemorySize, SMEM_BYTES);
    dim3 grid(N_TILES, 2);
    conv3d_v3_kernel<<<grid, 128, SMEM_BYTES>>>(input, weight, bias, out);
}

// round 6
// speedup vs baseline: 1.0005x; 1.0005x over previous
#include <cuda_runtime.h>

// ---------------------------------------------------------------------------
// AbstractConv3D v3: v2 + latency hiding. One block per 8x8x8 tile, 128 thr,
// thread owns a z-quad of 4 voxels. Per tap: hoist all 16 input LDS.128 into
// registers (64 regs), fully unroll ci4 so ptxas pipelines weight-LDS/dup/FMA2.
// 16 output channels x 4 voxels as 32 packed f32x2 accumulators (fma.rn.f32x2).
// ---------------------------------------------------------------------------

#define N_TOTAL 1846083
#define N_TILES 4059      // sum over levels of ceil(R/8)^3
#define PAD     20        // floats per voxel in smem halo (16 data + 4 pad)

__constant__ int c_R[16]    = {16,18,20,22,25,27,30,34,38,42,47,52,58,64,72,80};
__constant__ int c_off[16]  = {0,4096,9928,17928,28576,44201,63884,90884,
                               130188,185060,259148,362971,503579,698691,960835,1334083};
__constant__ int c_Tdim[16] = {2,3,3,3,4,4,4,5,5,6,6,7,8,8,9,10};
__constant__ int c_tcum[16] = {8,35,62,89,153,217,281,406,531,747,963,1306,1818,2330,3059,4059};

__device__ __forceinline__ unsigned long long ffma2(unsigned long long a,
                                                    unsigned long long b,
                                                    unsigned long long c) {
    unsigned long long d;
    asm("fma.rn.f32x2 %0, %1, %2, %3;" : "=l"(d) : "l"(a), "l"(b), "l"(c));
    return d;
}
__device__ __forceinline__ unsigned long long dup2(float x) {
    unsigned long long r;
    asm("mov.b64 %0, {%1, %1};" : "=l"(r) : "f"(x));
    return r;
}
__device__ __forceinline__ unsigned long long pack2(float lo, float hi) {
    unsigned long long r;
    asm("mov.b64 %0, {%1, %2};" : "=l"(r) : "f"(lo), "f"(hi));
    return r;
}

#define SMEM_IN_FLOATS (1000 * PAD)           // 20000 floats = 80 KB
#define SMEM_W_FLOATS  6912                   // 27*16*16     = 27.6 KB
#define SMEM_BYTES     ((SMEM_IN_FLOATS + SMEM_W_FLOATS) * 4)

__global__ void __launch_bounds__(128, 2)
conv3d_v3_kernel(const float* __restrict__ input,
                 const float* __restrict__ weight,
                 const float* __restrict__ bias,
                 float* __restrict__ out)
{
    extern __shared__ float smem[];
    float* s_in = smem;                       // [1000][PAD]
    float* s_w  = smem + SMEM_IN_FLOATS;      // [27][16][16]

    const int t   = blockIdx.x;
    const int b   = blockIdx.y;
    const int tid = threadIdx.x;

    // tile -> level
    int l = 0;
    while (t >= c_tcum[l]) ++l;
    const int base  = l ? c_tcum[l - 1] : 0;
    int local = t - base;
    const int T   = c_Tdim[l];
    const int R   = c_R[l];
    const int off = c_off[l];
    const int tx  = local % T;
    local /= T;
    const int ty  = local % T;
    const int tz  = local / T;
    const int x0 = tx * 8, y0 = ty * 8, z0 = tz * 8;

    // ---- load halo (zeros outside grid = SAME zero padding) ----
    const float* inbase = input + (size_t)b * N_TOTAL * 16;
    for (int h = tid; h < 1000; h += 128) {
        const int hx = h % 10;
        const int hq = h / 10;
        const int hy = hq % 10;
        const int hz = hq / 10;
        const int gx = x0 - 1 + hx;
        const int gy = y0 - 1 + hy;
        const int gz = z0 - 1 + hz;
        float* dst = &s_in[h * PAD];
        if ((unsigned)gx < (unsigned)R && (unsigned)gy < (unsigned)R &&
            (unsigned)gz < (unsigned)R) {
            const float4* src = (const float4*)(inbase +
                (size_t)(off + gx + gy * R + gz * R * R) * 16);
            ((float4*)dst)[0] = src[0];
            *(float4*)(dst + 4)  = src[1];
            *(float4*)(dst + 8)  = src[2];
            *(float4*)(dst + 12) = src[3];
        } else {
            const float4 z4 = make_float4(0.f, 0.f, 0.f, 0.f);
            ((float4*)dst)[0] = z4;
            *(float4*)(dst + 4)  = z4;
            *(float4*)(dst + 8)  = z4;
            *(float4*)(dst + 12) = z4;
        }
    }
    // ---- load weights for this level ----
    {
        const float4* wsrc = (const float4*)(weight + (size_t)l * SMEM_W_FLOATS);
        float4* wdst = (float4*)s_w;
        for (int i = tid; i < SMEM_W_FLOATS / 4; i += 128) wdst[i] = wsrc[i];
    }
    __syncthreads();

    // ---- compute: thread (x, y, zh) owns voxels z = 4*zh + {0,1,2,3} ----
    const int x  = tid & 7;
    const int y  = (tid >> 3) & 7;
    const int zh = tid >> 6;          // 0 or 1

    unsigned long long acc[4][8];
    {
        const float* bp = bias + l * 16;
        #pragma unroll
        for (int j = 0; j < 8; ++j) {
            const unsigned long long bj = pack2(bp[2 * j], bp[2 * j + 1]);
            acc[0][j] = bj; acc[1][j] = bj; acc[2][j] = bj; acc[3][j] = bj;
        }
    }

    const int hbase = ((4 * zh + 1) * 100 + (y + 1) * 10 + (x + 1)) * PAD;
    const int ZSTRIDE = 100 * PAD;

    #pragma unroll 1
    for (int tap = 0; tap < 27; ++tap) {
        const int dz  = tap / 9;
        const int rem = tap - dz * 9;
        const int dy  = rem / 3;
        const int dx  = rem - dy * 3;
        const int noff = ((dz - 1) * 100 + (dy - 1) * 10 + (dx - 1)) * PAD;

        const float* vb   = s_in + hbase + noff;
        const float* wtap = s_w + tap * 256;

        // hoist ALL input loads for this tap: 16 independent LDS.128
        float4 A[4][4];   // [ci4][voxel]
        #pragma unroll
        for (int ci4 = 0; ci4 < 4; ++ci4) {
            #pragma unroll
            for (int v = 0; v < 4; ++v) {
                A[ci4][v] = *(const float4*)(vb + v * ZSTRIDE + ci4 * 4);
            }
        }

        #pragma unroll
        for (int ci4 = 0; ci4 < 4; ++ci4) {
            const float av[4][4] = {
                {A[ci4][0].x, A[ci4][0].y, A[ci4][0].z, A[ci4][0].w},
                {A[ci4][1].x, A[ci4][1].y, A[ci4][1].z, A[ci4][1].w},
                {A[ci4][2].x, A[ci4][2].y, A[ci4][2].z, A[ci4][2].w},
                {A[ci4][3].x, A[ci4][3].y, A[ci4][3].z, A[ci4][3].w}};
            #pragma unroll
            for (int c = 0; c < 4; ++c) {
                const unsigned long long xd0 = dup2(av[0][c]);
                const unsigned long long xd1 = dup2(av[1][c]);
                const unsigned long long xd2 = dup2(av[2][c]);
                const unsigned long long xd3 = dup2(av[3][c]);
                const ulonglong2* wr = (const ulonglong2*)&wtap[(ci4 * 4 + c) * 16];
                #pragma unroll
                for (int q = 0; q < 4; ++q) {
                    const ulonglong2 w = wr[q];   // warp-uniform broadcast
                    acc[0][2 * q]     = ffma2(xd0, w.x, acc[0][2 * q]);
                    acc[0][2 * q + 1] = ffma2(xd0, w.y, acc[0][2 * q + 1]);
                    acc[1][2 * q]     = ffma2(xd1, w.x, acc[1][2 * q]);
                    acc[1][2 * q + 1] = ffma2(xd1, w.y, acc[1][2 * q + 1]);
                    acc[2][2 * q]     = ffma2(xd2, w.x, acc[2][2 * q]);
                    acc[2][2 * q + 1] = ffma2(xd2, w.y, acc[2][2 * q + 1]);
                    acc[3][2 * q]     = ffma2(xd3, w.x, acc[3][2 * q]);
                    acc[3][2 * q + 1] = ffma2(xd3, w.y, acc[3][2 * q + 1]);
                }
            }
        }
    }

    // ---- store 4 voxels (guarded against tile overhang) ----
    const int gx = x0 + x, gy = y0 + y;
    if (gx < R && gy < R) {
        float* outbase = out + (size_t)b * N_TOTAL * 16;
        const size_t xybase = (size_t)(off + gx + gy * R);
        #pragma unroll
        for (int k = 0; k < 4; ++k) {
            const int gz = z0 + 4 * zh + k;
            if (gz < R) {
                ulonglong2* o = (ulonglong2*)(outbase +
                    (xybase + (size_t)gz * R * R) * 16);
                o[0] = make_ulonglong2(acc[k][0], acc[k][1]);
                o[1] = make_ulonglong2(acc[k][2], acc[k][3]);
                o[2] = make_ulonglong2(acc[k][4], acc[k][5]);
                o[3] = make_ulonglong2(acc[k][6], acc[k][7]);
            }
        }
    }
}

extern "C" void kernel_launch(void* const* d_in, const int* in_sizes, int n_in,
                              void* d_out, int out_size)
{
    const float* input  = (const float*)d_in[0];
    const float* weight = (const float*)d_in[1];
    const float* bias   = (const float*)d_in[2];
    float* out = (float*)d_out;

    cudaFuncSetAttribute(conv3d_v3_kernel,
                         cudaFuncAttributeMaxDynamicSharedMemorySize, SMEM_BYTES);
    dim3 grid(N_TILES, 2);
    conv3d_v3_kernel<<<grid, 128, SMEM_BYTES>>>(input, weight, bias, out);
}

// round 7
// speedup vs baseline: 1.0013x; 1.0008x over previous
#include <cuda_runtime.h>

// ---------------------------------------------------------------------------
// AbstractConv3D v3: v2 + latency hiding. One block per 8x8x8 tile, 128 thr,
// thread owns a z-quad of 4 voxels. Per tap: hoist all 16 input LDS.128 into
// registers (64 regs), fully unroll ci4 so ptxas pipelines weight-LDS/dup/FMA2.
// 16 output channels x 4 voxels as 32 packed f32x2 accumulators (fma.rn.f32x2).
// ---------------------------------------------------------------------------

#define N_TOTAL 1846083
#define N_TILES 4059      // sum over levels of ceil(R/8)^3
#define PAD     20        // floats per voxel in smem halo (16 data + 4 pad)

__constant__ int c_R[16]    = {16,18,20,22,25,27,30,34,38,42,47,52,58,64,72,80};
__constant__ int c_off[16]  = {0,4096,9928,17928,28576,44201,63884,90884,
                               130188,185060,259148,362971,503579,698691,960835,1334083};
__constant__ int c_Tdim[16] = {2,3,3,3,4,4,4,5,5,6,6,7,8,8,9,10};
__constant__ int c_tcum[16] = {8,35,62,89,153,217,281,406,531,747,963,1306,1818,2330,3059,4059};

__device__ __forceinline__ unsigned long long ffma2(unsigned long long a,
                                                    unsigned long long b,
                                                    unsigned long long c) {
    unsigned long long d;
    asm("fma.rn.f32x2 %0, %1, %2, %3;" : "=l"(d) : "l"(a), "l"(b), "l"(c));
    return d;
}
__device__ __forceinline__ unsigned long long dup2(float x) {
    unsigned long long r;
    asm("mov.b64 %0, {%1, %1};" : "=l"(r) : "f"(x));
    return r;
}
__device__ __forceinline__ unsigned long long pack2(float lo, float hi) {
    unsigned long long r;
    asm("mov.b64 %0, {%1, %2};" : "=l"(r) : "f"(lo), "f"(hi));
    return r;
}

#define SMEM_IN_FLOATS (1000 * PAD)           // 20000 floats = 80 KB
#define SMEM_W_FLOATS  6912                   // 27*16*16     = 27.6 KB
#define SMEM_BYTES     ((SMEM_IN_FLOATS + SMEM_W_FLOATS) * 4)

__global__ void __launch_bounds__(128, 2)
conv3d_v3_kernel(const float* __restrict__ input,
                 const float* __restrict__ weight,
                 const float* __restrict__ bias,
                 float* __restrict__ out)
{
    extern __shared__ float smem[];
    float* s_in = smem;                       // [1000][PAD]
    float* s_w  = smem + SMEM_IN_FLOATS;      // [27][16][16]

    const int t   = blockIdx.x;
    const int b   = blockIdx.y;
    const int tid = threadIdx.x;

    // tile -> level
    int l = 0;
    while (t >= c_tcum[l]) ++l;
    const int base  = l ? c_tcum[l - 1] : 0;
    int local = t - base;
    const int T   = c_Tdim[l];
    const int R   = c_R[l];
    const int off = c_off[l];
    const int tx  = local % T;
    local /= T;
    const int ty  = local % T;
    const int tz  = local / T;
    const int x0 = tx * 8, y0 = ty * 8, z0 = tz * 8;

    // ---- load halo (zeros outside grid = SAME zero padding) ----
    const float* inbase = input + (size_t)b * N_TOTAL * 16;
    for (int h = tid; h < 1000; h += 128) {
        const int hx = h % 10;
        const int hq = h / 10;
        const int hy = hq % 10;
        const int hz = hq / 10;
        const int gx = x0 - 1 + hx;
        const int gy = y0 - 1 + hy;
        const int gz = z0 - 1 + hz;
        float* dst = &s_in[h * PAD];
        if ((unsigned)gx < (unsigned)R && (unsigned)gy < (unsigned)R &&
            (unsigned)gz < (unsigned)R) {
            const float4* src = (const float4*)(inbase +
                (size_t)(off + gx + gy * R + gz * R * R) * 16);
            ((float4*)dst)[0] = src[0];
            *(float4*)(dst + 4)  = src[1];
            *(float4*)(dst + 8)  = src[2];
            *(float4*)(dst + 12) = src[3];
        } else {
            const float4 z4 = make_float4(0.f, 0.f, 0.f, 0.f);
            ((float4*)dst)[0] = z4;
            *(float4*)(dst + 4)  = z4;
            *(float4*)(dst + 8)  = z4;
            *(float4*)(dst + 12) = z4;
        }
    }
    // ---- load weights for this level ----
    {
        const float4* wsrc = (const float4*)(weight + (size_t)l * SMEM_W_FLOATS);
        float4* wdst = (float4*)s_w;
        for (int i = tid; i < SMEM_W_FLOATS / 4; i += 128) wdst[i] = wsrc[i];
    }
    __syncthreads();

    // ---- compute: thread (x, y, zh) owns voxels z = 4*zh + {0,1,2,3} ----
    const int x  = tid & 7;
    const int y  = (tid >> 3) & 7;
    const int zh = tid >> 6;          // 0 or 1

    unsigned long long acc[4][8];
    {
        const float* bp = bias + l * 16;
        #pragma unroll
        for (int j = 0; j < 8; ++j) {
            const unsigned long long bj = pack2(bp[2 * j], bp[2 * j + 1]);
            acc[0][j] = bj; acc[1][j] = bj; acc[2][j] = bj; acc[3][j] = bj;
        }
    }

    const int hbase = ((4 * zh + 1) * 100 + (y + 1) * 10 + (x + 1)) * PAD;
    const int ZSTRIDE = 100 * PAD;

    #pragma unroll 1
    for (int tap = 0; tap < 27; ++tap) {
        const int dz  = tap / 9;
        const int rem = tap - dz * 9;
        const int dy  = rem / 3;
        const int dx  = rem - dy * 3;
        const int noff = ((dz - 1) * 100 + (dy - 1) * 10 + (dx - 1)) * PAD;

        const float* vb   = s_in + hbase + noff;
        const float* wtap = s_w + tap * 256;

        // hoist ALL input loads for this tap: 16 independent LDS.128
        float4 A[4][4];   // [ci4][voxel]
        #pragma unroll
        for (int ci4 = 0; ci4 < 4; ++ci4) {
            #pragma unroll
            for (int v = 0; v < 4; ++v) {
                A[ci4][v] = *(const float4*)(vb + v * ZSTRIDE + ci4 * 4);
            }
        }

        #pragma unroll
        for (int ci4 = 0; ci4 < 4; ++ci4) {
            const float av[4][4] = {
                {A[ci4][0].x, A[ci4][0].y, A[ci4][0].z, A[ci4][0].w},
                {A[ci4][1].x, A[ci4][1].y, A[ci4][1].z, A[ci4][1].w},
                {A[ci4][2].x, A[ci4][2].y, A[ci4][2].z, A[ci4][2].w},
                {A[ci4][3].x, A[ci4][3].y, A[ci4][3].z, A[ci4][3].w}};
            #pragma unroll
            for (int c = 0; c < 4; ++c) {
                const unsigned long long xd0 = dup2(av[0][c]);
                const unsigned long long xd1 = dup2(av[1][c]);
                const unsigned long long xd2 = dup2(av[2][c]);
                const unsigned long long xd3 = dup2(av[3][c]);
                const ulonglong2* wr = (const ulonglong2*)&wtap[(ci4 * 4 + c) * 16];
                #pragma unroll
                for (int q = 0; q < 4; ++q) {
                    const ulonglong2 w = wr[q];   // warp-uniform broadcast
                    acc[0][2 * q]     = ffma2(xd0, w.x, acc[0][2 * q]);
                    acc[0][2 * q + 1] = ffma2(xd0, w.y, acc[0][2 * q + 1]);
                    acc[1][2 * q]     = ffma2(xd1, w.x, acc[1][2 * q]);
                    acc[1][2 * q + 1] = ffma2(xd1, w.y, acc[1][2 * q + 1]);
                    acc[2][2 * q]     = ffma2(xd2, w.x, acc[2][2 * q]);
                    acc[2][2 * q + 1] = ffma2(xd2, w.y, acc[2][2 * q + 1]);
                    acc[3][2 * q]     = ffma2(xd3, w.x, acc[3][2 * q]);
                    acc[3][2 * q + 1] = ffma2(xd3, w.y, acc[3][2 * q + 1]);
                }
            }
        }
    }

    // ---- store 4 voxels (guarded against tile overhang) ----
    const int gx = x0 + x, gy = y0 + y;
    if (gx < R && gy < R) {
        float* outbase = out + (size_t)b * N_TOTAL * 16;
        const size_t xybase = (size_t)(off + gx + gy * R);
        #pragma unroll
        for (int k = 0; k < 4; ++k) {
            const int gz = z0 + 4 * zh + k;
            if (gz < R) {
                ulonglong2* o = (ulonglong2*)(outbase +
                    (xybase + (size_t)gz * R * R) * 16);
                o[0] = make_ulonglong2(acc[k][0], acc[k][1]);
                o[1] = make_ulonglong2(acc[k][2], acc[k][3]);
                o[2] = make_ulonglong2(acc[k][4], acc[k][5]);
                o[3] = make_ulonglong2(acc[k][6], acc[k][7]);
            }
        }
    }
}

extern "C" void kernel_launch(void* const* d_in, const int* in_sizes, int n_in,
                              void* d_out, int out_size)
{
    const float* input  = (const float*)d_in[0];
    const float* weight = (const float*)d_in[1];
    const float* bias   = (const float*)d_in[2];
    float* out = (float*)d_out;

    cudaFuncSetAttribute(conv3d_v3_kernel,
                         cudaFuncAttributeMaxDynamicSharedMemorySize, SMEM_BYTES);
    dim3 grid(N_TILES, 2);
    conv3d_v3_kernel<<<grid, 128, SMEM_BYTES>>>(input, weight, bias, out);
}

// round 11
// speedup vs baseline: 1.6835x; 1.6813x over previous
#include <cuda_runtime.h>
#include <cuda_bf16.h>

// ---------------------------------------------------------------------------
// AbstractConv3D v5: implicit GEMM on mma.sync (HMMA, no 'a'-gated PTX).
// Halo stored as linear rows (32B = 16 bf16 ch); tap shift = per-lane row
// offset fed to ldmatrix => zero im2col copies, zero junk rows.
// fp32 = bf16 hi + lo; 3 MMAs per tap (hi*whi + lo*whi + hi*wlo), f32 accum.
// Block = 8x8x4 tile (256 voxels = 16 m16 fragments, 2 per warp), N=16 co.
// ---------------------------------------------------------------------------

#define N_TOTAL   1846083
#define N_TILES   7894
#define SLAB      19456        // 608 rows * 32 B (bf16 hi slab; lo slab follows)
#define B_OFF     (2 * SLAB)   // 38912
#define B_U2      3456         // 27 taps * 2 parts * 2 n8 * 32 lanes (uint2)
#define SMEM_BYTES (B_OFF + B_U2 * 8)   // 66560

__constant__ int c_R[16]    = {16,18,20,22,25,27,30,34,38,42,47,52,58,64,72,80};
__constant__ int c_off[16]  = {0,4096,9928,17928,28576,44201,63884,90884,
                               130188,185060,259148,362971,503579,698691,960835,1334083};
__constant__ int c_Txy[16]  = {2,3,3,3,4,4,4,5,5,6,6,7,8,8,9,10};
__constant__ int c_tcum[16] = {16,61,106,160,272,384,512,737,987,1383,1815,2452,3412,4436,5894,7894};
__constant__ int c_toff[27] = {-111,-110,-109,-101,-100,-99,-91,-90,-89,
                               -11,-10,-9,-1,0,1,9,10,11,
                               89,90,91,99,100,101,109,110,111};

// prepped weights: per (level, tap, part, n8): 32 lanes x uint2 (mma B frags)
__device__ uint2 g_Bw[16 * B_U2];

// ---------------- PTX helpers (all plain sm_80-era instructions) ----------
__device__ __forceinline__ unsigned smem_u32(const void* p) {
    unsigned a;
    asm("{ .reg .u64 t; cvta.to.shared.u64 t, %1; cvt.u32.u64 %0, t; }"
        : "=r"(a) : "l"(p));
    return a;
}
__device__ __forceinline__ void ldsm_x4(unsigned a[4], unsigned addr) {
    asm volatile("ldmatrix.sync.aligned.m8n8.x4.shared.b16 {%0,%1,%2,%3}, [%4];"
        : "=r"(a[0]), "=r"(a[1]), "=r"(a[2]), "=r"(a[3]) : "r"(addr));
}
__device__ __forceinline__ void mma_bf16(float c[4], const unsigned a[4],
                                         unsigned b0, unsigned b1) {
    asm volatile(
        "mma.sync.aligned.m16n8k16.row.col.f32.bf16.bf16.f32 "
        "{%0,%1,%2,%3}, {%4,%5,%6,%7}, {%8,%9}, {%0,%1,%2,%3};"
        : "+f"(c[0]), "+f"(c[1]), "+f"(c[2]), "+f"(c[3])
        : "r"(a[0]), "r"(a[1]), "r"(a[2]), "r"(a[3]), "r"(b0), "r"(b1));
}

// ---------------- weight prep: f32 -> bf16 hi/lo in mma-B fragment order ---
// entry idx = (((l*27 + tap)*2 + part)*2 + n8)*32 + lane
__global__ void prep_weights(const float* __restrict__ w) {
    const int idx = blockIdx.x * 256 + threadIdx.x;
    if (idx >= 16 * B_U2) return;
    const int lane = idx & 31;
    const int n8   = (idx >> 5) & 1;
    const int part = (idx >> 6) & 1;
    const int tap  = (idx >> 7) % 27;
    const int l    = idx / B_U2;
    const int co   = n8 * 8 + (lane >> 2);
    const int ci0  = (lane & 3) * 2;
    const float* wb = w + (size_t)(l * 27 + tap) * 256;   // [ci][co]
    float v[4] = { wb[ci0 * 16 + co],       wb[(ci0 + 1) * 16 + co],
                   wb[(ci0 + 8) * 16 + co], wb[(ci0 + 9) * 16 + co] };
    __nv_bfloat16 e[4];
    #pragma unroll
    for (int i = 0; i < 4; ++i) {
        const __nv_bfloat16 hi = __float2bfloat16(v[i]);
        e[i] = part == 0 ? hi : __float2bfloat16(v[i] - __bfloat162float(hi));
    }
    __nv_bfloat162 r0 = __nv_bfloat162(e[0], e[1]);   // low = smaller k
    __nv_bfloat162 r1 = __nv_bfloat162(e[2], e[3]);
    g_Bw[idx] = make_uint2(*reinterpret_cast<unsigned*>(&r0),
                           *reinterpret_cast<unsigned*>(&r1));
}

// ---------------- main kernel ----------------
__global__ void __launch_bounds__(256, 3)
conv3d_hmma_kernel(const float* __restrict__ input,
                   const float* __restrict__ bias,
                   float* __restrict__ out)
{
    extern __shared__ char smem[];
    const int tid = threadIdx.x;
    const int t = blockIdx.x, bb = blockIdx.y;

    // tile -> level
    int l = 0;
    while (t >= c_tcum[l]) ++l;
    int local = t - (l ? c_tcum[l - 1] : 0);
    const int Txy = c_Txy[l], R = c_R[l], off = c_off[l];
    const int tx = local % Txy; local /= Txy;
    const int ty = local % Txy; const int tz = local / Txy;
    const int x0 = tx * 8, y0 = ty * 8, z0 = tz * 4;

    // ---- stage B fragments for this level ----
    {
        const uint2* src = g_Bw + (size_t)l * B_U2;
        uint2* dst = (uint2*)(smem + B_OFF);
        for (int i = tid; i < B_U2; i += 256) dst[i] = src[i];
    }

    // ---- stage + split halo: 600 rows of 16ch, hi slab + lo slab ----
    const float* inbase = input + (size_t)bb * N_TOTAL * 16;
    for (int h = tid; h < 608; h += 256) {
        float vals[16];
        bool inb = false;
        if (h < 600) {
            const int hx = h % 10, hq = h / 10, hy = hq % 10, hz = hq / 10;
            const int gx = x0 - 1 + hx, gy = y0 - 1 + hy, gz = z0 - 1 + hz;
            inb = (unsigned)gx < (unsigned)R && (unsigned)gy < (unsigned)R &&
                  (unsigned)gz < (unsigned)R;
            if (inb) {
                const float4* s = (const float4*)(inbase +
                    (size_t)(off + gx + gy * R + gz * R * R) * 16);
                const float4 v0 = s[0], v1 = s[1], v2 = s[2], v3 = s[3];
                vals[0]=v0.x; vals[1]=v0.y; vals[2]=v0.z; vals[3]=v0.w;
                vals[4]=v1.x; vals[5]=v1.y; vals[6]=v1.z; vals[7]=v1.w;
                vals[8]=v2.x; vals[9]=v2.y; vals[10]=v2.z; vals[11]=v2.w;
                vals[12]=v3.x; vals[13]=v3.y; vals[14]=v3.z; vals[15]=v3.w;
            }
        }
        if (!inb)
            #pragma unroll
            for (int i = 0; i < 16; ++i) vals[i] = 0.f;

        unsigned hiw[8], low[8];
        #pragma unroll
        for (int p = 0; p < 8; ++p) {
            const float a = vals[2 * p], b = vals[2 * p + 1];
            __nv_bfloat162 hh = __floats2bfloat162_rn(a, b);
            const float ra = a - __bfloat162float(__low2bfloat16(hh));
            const float rb = b - __bfloat162float(__high2bfloat16(hh));
            __nv_bfloat162 ll = __floats2bfloat162_rn(ra, rb);
            hiw[p] = *reinterpret_cast<unsigned*>(&hh);
            low[p] = *reinterpret_cast<unsigned*>(&ll);
        }
        char* hrow = smem + (size_t)h * 32;
        *(uint4*)(hrow)            = make_uint4(hiw[0], hiw[1], hiw[2], hiw[3]);
        *(uint4*)(hrow + 16)       = make_uint4(hiw[4], hiw[5], hiw[6], hiw[7]);
        *(uint4*)(hrow + SLAB)     = make_uint4(low[0], low[1], low[2], low[3]);
        *(uint4*)(hrow + SLAB + 16)= make_uint4(low[4], low[5], low[6], low[7]);
    }
    __syncthreads();

    // ---- per-lane ldmatrix base addresses (2 m16 groups per warp) ----
    const int w    = tid >> 5;
    const int lane = tid & 31;
    const unsigned sbase = smem_u32(smem);
    unsigned addrA[2];
    #pragma unroll
    for (int g = 0; g < 2; ++g) {
        const int v = w * 32 + g * 16 + (lane & 15);
        const int x = v & 7, y = (v >> 3) & 7, z = v >> 6;
        const int h = (x + 1) + 10 * (y + 1) + 100 * (z + 1);
        addrA[g] = sbase + (unsigned)(h * 32) + ((lane >> 4) << 4);
    }

    float c[2][2][4];
    #pragma unroll
    for (int g = 0; g < 2; ++g)
        #pragma unroll
        for (int n = 0; n < 2; ++n)
            #pragma unroll
            for (int i = 0; i < 4; ++i) c[g][n][i] = 0.f;

    const uint2* sB = (const uint2*)(smem + B_OFF) + lane;

    #pragma unroll 1
    for (int tap = 0; tap < 27; ++tap) {
        const int sh = c_toff[tap] * 32;
        const uint2 bh0 = sB[tap * 128 +  0];   // whi, co 0-7
        const uint2 bh1 = sB[tap * 128 + 32];   // whi, co 8-15
        const uint2 bl0 = sB[tap * 128 + 64];   // wlo, co 0-7
        const uint2 bl1 = sB[tap * 128 + 96];   // wlo, co 8-15
        #pragma unroll
        for (int g = 0; g < 2; ++g) {
            unsigned A0[4], A1[4];
            ldsm_x4(A0, addrA[g] + sh);          // A hi
            ldsm_x4(A1, addrA[g] + sh + SLAB);   // A lo
            mma_bf16(c[g][0], A0, bh0.x, bh0.y);
            mma_bf16(c[g][1], A0, bh1.x, bh1.y);
            mma_bf16(c[g][0], A1, bh0.x, bh0.y);
            mma_bf16(c[g][1], A1, bh1.x, bh1.y);
            mma_bf16(c[g][0], A0, bl0.x, bl0.y);
            mma_bf16(c[g][1], A0, bl1.x, bl1.y);
        }
    }

    // ---- epilogue: scatter C fragments + bias ----
    const int gid = lane >> 2;
    const int cp  = (lane & 3) * 2;
    const float2 bv0 = *(const float2*)(bias + l * 16 + cp);
    const float2 bv1 = *(const float2*)(bias + l * 16 + 8 + cp);
    float* outbase = out + (size_t)bb * N_TOTAL * 16;

    #pragma unroll
    for (int g = 0; g < 2; ++g) {
        #pragma unroll
        for (int rs = 0; rs < 2; ++rs) {
            const int v = w * 32 + g * 16 + gid + rs * 8;
            const int x = v & 7, y = (v >> 3) & 7, z = v >> 6;
            const int gx = x0 + x, gy = y0 + y, gz = z0 + z;
            if (gx < R && gy < R && gz < R) {
                float* o = outbase + (size_t)(off + gx + gy * R + gz * R * R) * 16;
                *(float2*)(o + cp) =
                    make_float2(c[g][0][rs * 2]     + bv0.x,
                                c[g][0][rs * 2 + 1] + bv0.y);
                *(float2*)(o + 8 + cp) =
                    make_float2(c[g][1][rs * 2]     + bv1.x,
                                c[g][1][rs * 2 + 1] + bv1.y);
            }
        }
    }
}

extern "C" void kernel_launch(void* const* d_in, const int* in_sizes, int n_in,
                              void* d_out, int out_size)
{
    const float* input  = (const float*)d_in[0];
    const float* weight = (const float*)d_in[1];
    const float* bias   = (const float*)d_in[2];
    float* out = (float*)d_out;

    prep_weights<<<216, 256>>>(weight);

    cudaFuncSetAttribute(conv3d_hmma_kernel,
                         cudaFuncAttributeMaxDynamicSharedMemorySize, SMEM_BYTES);
    dim3 grid(N_TILES, 2);
    conv3d_hmma_kernel<<<grid, 256, SMEM_BYTES>>>(input, bias, out);
}

// round 12
// speedup vs baseline: 2.8821x; 1.7120x over previous
#include <cuda_runtime.h>
#include <cuda_fp16.h>

// ---------------------------------------------------------------------------
// AbstractConv3D v6: implicit GEMM on mma.sync fp16, 2-term emulation.
// out = (x_hi + x_lo) * w_hi  (fp16 splits, f32 accum) -> exact x times
// fp16-rounded w: rel err ~2^-11/sqrt(3) RMS ~ 3e-4 << 1e-3.
// Halo rows XOR-swizzled so ldmatrix is bank-conflict-free:
//   chunk s of row h stored at h*32 + ((s ^ ((h>>2)&1))<<4).
// Block = 8x8x4 tile, 8 warps, tap shift = per-lane ldmatrix row offset.
// ---------------------------------------------------------------------------

#define N_TOTAL   1846083
#define N_TILES   7894
#define SLAB      19456              // 608 rows * 32 B (fp16 hi slab; lo follows)
#define B_OFF     (2 * SLAB)         // 38912
#define B_U2      1728               // 27 taps * 2 n8 * 32 lanes (uint2, w_hi only)
#define SMEM_BYTES (B_OFF + B_U2 * 8)   // 52736 -> 4 blocks/SM

__constant__ int c_R[16]    = {16,18,20,22,25,27,30,34,38,42,47,52,58,64,72,80};
__constant__ int c_off[16]  = {0,4096,9928,17928,28576,44201,63884,90884,
                               130188,185060,259148,362971,503579,698691,960835,1334083};
__constant__ int c_Txy[16]  = {2,3,3,3,4,4,4,5,5,6,6,7,8,8,9,10};
__constant__ int c_tcum[16] = {16,61,106,160,272,384,512,737,987,1383,1815,2452,3412,4436,5894,7894};
__constant__ int c_toff[27] = {-111,-110,-109,-101,-100,-99,-91,-90,-89,
                               -11,-10,-9,-1,0,1,9,10,11,
                               89,90,91,99,100,101,109,110,111};

// prepped weights (fp16 hi): per (level, tap, n8): 32 lanes x uint2 B frags
__device__ uint2 g_Bw[16 * B_U2];

// ---------------- PTX helpers ----------------
__device__ __forceinline__ unsigned smem_u32(const void* p) {
    unsigned a;
    asm("{ .reg .u64 t; cvta.to.shared.u64 t, %1; cvt.u32.u64 %0, t; }"
        : "=r"(a) : "l"(p));
    return a;
}
__device__ __forceinline__ void ldsm_x4(unsigned a[4], unsigned addr) {
    asm volatile("ldmatrix.sync.aligned.m8n8.x4.shared.b16 {%0,%1,%2,%3}, [%4];"
        : "=r"(a[0]), "=r"(a[1]), "=r"(a[2]), "=r"(a[3]) : "r"(addr));
}
__device__ __forceinline__ void mma_f16(float c[4], const unsigned a[4],
                                        unsigned b0, unsigned b1) {
    asm volatile(
        "mma.sync.aligned.m16n8k16.row.col.f32.f16.f16.f32 "
        "{%0,%1,%2,%3}, {%4,%5,%6,%7}, {%8,%9}, {%0,%1,%2,%3};"
        : "+f"(c[0]), "+f"(c[1]), "+f"(c[2]), "+f"(c[3])
        : "r"(a[0]), "r"(a[1]), "r"(a[2]), "r"(a[3]), "r"(b0), "r"(b1));
}

// ---------------- weight prep: f32 -> fp16 hi in mma-B fragment order ------
// entry idx = ((l*27 + tap)*2 + n8)*32 + lane
__global__ void prep_weights(const float* __restrict__ w) {
    const int idx = blockIdx.x * 256 + threadIdx.x;
    if (idx >= 16 * B_U2) return;
    const int lane = idx & 31;
    const int n8   = (idx >> 5) & 1;
    const int tap  = (idx >> 6) % 27;
    const int l    = idx / B_U2;
    const int co   = n8 * 8 + (lane >> 2);
    const int ci0  = (lane & 3) * 2;
    const float* wb = w + (size_t)(l * 27 + tap) * 256;   // [ci][co]
    __half2 r0 = __floats2half2_rn(wb[ci0 * 16 + co],       wb[(ci0 + 1) * 16 + co]);
    __half2 r1 = __floats2half2_rn(wb[(ci0 + 8) * 16 + co], wb[(ci0 + 9) * 16 + co]);
    g_Bw[idx] = make_uint2(*reinterpret_cast<unsigned*>(&r0),
                           *reinterpret_cast<unsigned*>(&r1));
}

// ---------------- main kernel ----------------
__global__ void __launch_bounds__(256, 4)
conv3d_hmma2_kernel(const float* __restrict__ input,
                    const float* __restrict__ bias,
                    float* __restrict__ out)
{
    extern __shared__ char smem[];
    const int tid = threadIdx.x;
    const int t = blockIdx.x, bb = blockIdx.y;

    // tile -> level
    int l = 0;
    while (t >= c_tcum[l]) ++l;
    int local = t - (l ? c_tcum[l - 1] : 0);
    const int Txy = c_Txy[l], R = c_R[l], off = c_off[l];
    const int tx = local % Txy; local /= Txy;
    const int ty = local % Txy; const int tz = local / Txy;
    const int x0 = tx * 8, y0 = ty * 8, z0 = tz * 4;

    // ---- stage B fragments for this level ----
    {
        const uint2* src = g_Bw + (size_t)l * B_U2;
        uint2* dst = (uint2*)(smem + B_OFF);
        for (int i = tid; i < B_U2; i += 256) dst[i] = src[i];
    }

    // ---- stage + split halo: hi slab + lo slab, XOR-swizzled chunks ----
    const float* inbase = input + (size_t)bb * N_TOTAL * 16;
    for (int h = tid; h < 608; h += 256) {
        float vals[16];
        bool inb = false;
        if (h < 600) {
            const int hx = h % 10, hq = h / 10, hy = hq % 10, hz = hq / 10;
            const int gx = x0 - 1 + hx, gy = y0 - 1 + hy, gz = z0 - 1 + hz;
            inb = (unsigned)gx < (unsigned)R && (unsigned)gy < (unsigned)R &&
                  (unsigned)gz < (unsigned)R;
            if (inb) {
                const float4* s = (const float4*)(inbase +
                    (size_t)(off + gx + gy * R + gz * R * R) * 16);
                const float4 v0 = s[0], v1 = s[1], v2 = s[2], v3 = s[3];
                vals[0]=v0.x; vals[1]=v0.y; vals[2]=v0.z; vals[3]=v0.w;
                vals[4]=v1.x; vals[5]=v1.y; vals[6]=v1.z; vals[7]=v1.w;
                vals[8]=v2.x; vals[9]=v2.y; vals[10]=v2.z; vals[11]=v2.w;
                vals[12]=v3.x; vals[13]=v3.y; vals[14]=v3.z; vals[15]=v3.w;
            }
        }
        if (!inb)
            #pragma unroll
            for (int i = 0; i < 16; ++i) vals[i] = 0.f;

        unsigned hiw[8], low[8];
        #pragma unroll
        for (int p = 0; p < 8; ++p) {
            const float a = vals[2 * p], b = vals[2 * p + 1];
            __half2 hh = __floats2half2_rn(a, b);
            const float ra = a - __low2float(hh);
            const float rb = b - __high2float(hh);
            __half2 ll = __floats2half2_rn(ra, rb);
            hiw[p] = *reinterpret_cast<unsigned*>(&hh);
            low[p] = *reinterpret_cast<unsigned*>(&ll);
        }
        const unsigned swb = (unsigned)((h & 4) << 2);   // 0 or 16
        char* hrow = smem + (size_t)h * 32;
        *(uint4*)(hrow + swb)               = make_uint4(hiw[0], hiw[1], hiw[2], hiw[3]);
        *(uint4*)(hrow + (swb ^ 16))        = make_uint4(hiw[4], hiw[5], hiw[6], hiw[7]);
        *(uint4*)(hrow + SLAB + swb)        = make_uint4(low[0], low[1], low[2], low[3]);
        *(uint4*)(hrow + SLAB + (swb ^ 16)) = make_uint4(low[4], low[5], low[6], low[7]);
    }
    __syncthreads();

    // ---- per-lane ldmatrix base rows (2 m16 groups per warp) ----
    const int w    = tid >> 5;
    const int lane = tid & 31;
    const unsigned sbase = smem_u32(smem);
    const unsigned s16 = (unsigned)((lane >> 4) << 4);   // which 16B k-half
    int hrow0[2];
    #pragma unroll
    for (int g = 0; g < 2; ++g) {
        const int v = w * 32 + g * 16 + (lane & 15);
        const int x = v & 7, y = (v >> 3) & 7, z = v >> 6;
        hrow0[g] = (x + 1) + 10 * (y + 1) + 100 * (z + 1);
    }

    float c[2][2][4];
    #pragma unroll
    for (int g = 0; g < 2; ++g)
        #pragma unroll
        for (int n = 0; n < 2; ++n)
            #pragma unroll
            for (int i = 0; i < 4; ++i) c[g][n][i] = 0.f;

    const uint2* sB = (const uint2*)(smem + B_OFF) + lane;

    #pragma unroll 1
    for (int tap = 0; tap < 27; ++tap) {
        const int toff = c_toff[tap];
        const uint2 bh0 = sB[tap * 64 +  0];   // w_hi, co 0-7
        const uint2 bh1 = sB[tap * 64 + 32];   // w_hi, co 8-15
        #pragma unroll
        for (int g = 0; g < 2; ++g) {
            const int h1 = hrow0[g] + toff;
            const unsigned swb = (unsigned)((h1 & 4) << 2);
            const unsigned addr = sbase + (unsigned)(h1 * 32) + (s16 ^ swb);
            unsigned A0[4], A1[4];
            ldsm_x4(A0, addr);          // x_hi
            ldsm_x4(A1, addr + SLAB);   // x_lo
            mma_f16(c[g][0], A0, bh0.x, bh0.y);
            mma_f16(c[g][1], A0, bh1.x, bh1.y);
            mma_f16(c[g][0], A1, bh0.x, bh0.y);
            mma_f16(c[g][1], A1, bh1.x, bh1.y);
        }
    }

    // ---- epilogue: scatter C fragments + bias ----
    const int gid = lane >> 2;
    const int cp  = (lane & 3) * 2;
    const float2 bv0 = *(const float2*)(bias + l * 16 + cp);
    const float2 bv1 = *(const float2*)(bias + l * 16 + 8 + cp);
    float* outbase = out + (size_t)bb * N_TOTAL * 16;

    #pragma unroll
    for (int g = 0; g < 2; ++g) {
        #pragma unroll
        for (int rs = 0; rs < 2; ++rs) {
            const int v = w * 32 + g * 16 + gid + rs * 8;
            const int x = v & 7, y = (v >> 3) & 7, z = v >> 6;
            const int gx = x0 + x, gy = y0 + y, gz = z0 + z;
            if (gx < R && gy < R && gz < R) {
                float* o = outbase + (size_t)(off + gx + gy * R + gz * R * R) * 16;
                *(float2*)(o + cp) =
                    make_float2(c[g][0][rs * 2]     + bv0.x,
                                c[g][0][rs * 2 + 1] + bv0.y);
                *(float2*)(o + 8 + cp) =
                    make_float2(c[g][1][rs * 2]     + bv1.x,
                                c[g][1][rs * 2 + 1] + bv1.y);
            }
        }
    }
}

extern "C" void kernel_launch(void* const* d_in, const int* in_sizes, int n_in,
                              void* d_out, int out_size)
{
    const float* input  = (const float*)d_in[0];
    const float* weight = (const float*)d_in[1];
    const float* bias   = (const float*)d_in[2];
    float* out = (float*)d_out;

    prep_weights<<<108, 256>>>(weight);

    cudaFuncSetAttribute(conv3d_hmma2_kernel,
                         cudaFuncAttributeMaxDynamicSharedMemorySize, SMEM_BYTES);
    dim3 grid(N_TILES, 2);
    conv3d_hmma2_kernel<<<grid, 256, SMEM_BYTES>>>(input, bias, out);
}

// round 13
// speedup vs baseline: 4.0038x; 1.3892x over previous
#include <cuda_runtime.h>
#include <cuda_fp16.h>

// ---------------------------------------------------------------------------
// AbstractConv3D v7: implicit GEMM on mma.sync fp16, single-term.
// out = fp16(x) * fp16(w), f32 accumulate. rel err ~3e-4 << 1e-3.
// Halo rows (32B = 16 fp16 ch) XOR-swizzled: chunk s of row h at
// h*32 + ((s ^ ((h>>2)&1))<<4)  -> conflict-free ldmatrix.
// Block = 8x8x4 tile, 8 warps; tap shift = per-lane ldmatrix row offset.
// 2 MMAs per (tap, m16-group): A once, B packed as one uint4/lane.
// ---------------------------------------------------------------------------

#define N_TOTAL   1846083
#define N_TILES   7894
#define SLAB      19456              // 608 rows * 32 B (fp16 halo)
#define B_OFF     SLAB               // 19456
#define B_U4      864                // 27 taps * 32 lanes (uint4: both n8 frags)
#define SMEM_BYTES (B_OFF + B_U4 * 16)   // 33280 B

__constant__ int c_R[16]    = {16,18,20,22,25,27,30,34,38,42,47,52,58,64,72,80};
__constant__ int c_off[16]  = {0,4096,9928,17928,28576,44201,63884,90884,
                               130188,185060,259148,362971,503579,698691,960835,1334083};
__constant__ int c_Txy[16]  = {2,3,3,3,4,4,4,5,5,6,6,7,8,8,9,10};
__constant__ int c_tcum[16] = {16,61,106,160,272,384,512,737,987,1383,1815,2452,3412,4436,5894,7894};
__constant__ int c_toff[27] = {-111,-110,-109,-101,-100,-99,-91,-90,-89,
                               -11,-10,-9,-1,0,1,9,10,11,
                               89,90,91,99,100,101,109,110,111};

// prepped weights (fp16): per (level, tap): 32 lanes x uint4 (n8=0 pair, n8=1 pair)
__device__ uint4 g_Bw[16 * B_U4];

// ---------------- PTX helpers ----------------
__device__ __forceinline__ unsigned smem_u32(const void* p) {
    unsigned a;
    asm("{ .reg .u64 t; cvta.to.shared.u64 t, %1; cvt.u32.u64 %0, t; }"
        : "=r"(a) : "l"(p));
    return a;
}
__device__ __forceinline__ void ldsm_x4(unsigned a[4], unsigned addr) {
    asm volatile("ldmatrix.sync.aligned.m8n8.x4.shared.b16 {%0,%1,%2,%3}, [%4];"
        : "=r"(a[0]), "=r"(a[1]), "=r"(a[2]), "=r"(a[3]) : "r"(addr));
}
__device__ __forceinline__ void mma_f16(float c[4], const unsigned a[4],
                                        unsigned b0, unsigned b1) {
    asm volatile(
        "mma.sync.aligned.m16n8k16.row.col.f32.f16.f16.f32 "
        "{%0,%1,%2,%3}, {%4,%5,%6,%7}, {%8,%9}, {%0,%1,%2,%3};"
        : "+f"(c[0]), "+f"(c[1]), "+f"(c[2]), "+f"(c[3])
        : "r"(a[0]), "r"(a[1]), "r"(a[2]), "r"(a[3]), "r"(b0), "r"(b1));
}

// ---------------- weight prep: f32 -> fp16 in packed mma-B fragment order --
// entry idx = (l*27 + tap)*32 + lane ; uint4 = (n8=0: k0k1,k8k9 ; n8=1: same)
__global__ void prep_weights(const float* __restrict__ w) {
    const int idx = blockIdx.x * 256 + threadIdx.x;
    if (idx >= 16 * B_U4) return;
    const int lane = idx & 31;
    const int tap  = (idx >> 5) % 27;
    const int l    = idx / B_U4;
    const int ci0  = (lane & 3) * 2;
    const float* wb = w + (size_t)(l * 27 + tap) * 256;   // [ci][co]
    unsigned r[4];
    #pragma unroll
    for (int n8 = 0; n8 < 2; ++n8) {
        const int co = n8 * 8 + (lane >> 2);
        __half2 p0 = __floats2half2_rn(wb[ci0 * 16 + co],       wb[(ci0 + 1) * 16 + co]);
        __half2 p1 = __floats2half2_rn(wb[(ci0 + 8) * 16 + co], wb[(ci0 + 9) * 16 + co]);
        r[2 * n8]     = *reinterpret_cast<unsigned*>(&p0);
        r[2 * n8 + 1] = *reinterpret_cast<unsigned*>(&p1);
    }
    g_Bw[idx] = make_uint4(r[0], r[1], r[2], r[3]);
}

// ---------------- main kernel ----------------
__global__ void __launch_bounds__(256, 4)
conv3d_hmma3_kernel(const float* __restrict__ input,
                    const float* __restrict__ bias,
                    float* __restrict__ out)
{
    extern __shared__ char smem[];
    const int tid = threadIdx.x;
    const int t = blockIdx.x, bb = blockIdx.y;

    // tile -> level
    int l = 0;
    while (t >= c_tcum[l]) ++l;
    int local = t - (l ? c_tcum[l - 1] : 0);
    const int Txy = c_Txy[l], R = c_R[l], off = c_off[l];
    const int tx = local % Txy; local /= Txy;
    const int ty = local % Txy; const int tz = local / Txy;
    const int x0 = tx * 8, y0 = ty * 8, z0 = tz * 4;

    // ---- stage B fragments for this level ----
    {
        const uint4* src = g_Bw + (size_t)l * B_U4;
        uint4* dst = (uint4*)(smem + B_OFF);
        for (int i = tid; i < B_U4; i += 256) dst[i] = src[i];
    }

    // ---- stage halo as fp16, XOR-swizzled chunks ----
    const float* inbase = input + (size_t)bb * N_TOTAL * 16;
    for (int h = tid; h < 608; h += 256) {
        float vals[16];
        bool inb = false;
        if (h < 600) {
            const int hx = h % 10, hq = h / 10, hy = hq % 10, hz = hq / 10;
            const int gx = x0 - 1 + hx, gy = y0 - 1 + hy, gz = z0 - 1 + hz;
            inb = (unsigned)gx < (unsigned)R && (unsigned)gy < (unsigned)R &&
                  (unsigned)gz < (unsigned)R;
            if (inb) {
                const float4* s = (const float4*)(inbase +
                    (size_t)(off + gx + gy * R + gz * R * R) * 16);
                const float4 v0 = s[0], v1 = s[1], v2 = s[2], v3 = s[3];
                vals[0]=v0.x; vals[1]=v0.y; vals[2]=v0.z; vals[3]=v0.w;
                vals[4]=v1.x; vals[5]=v1.y; vals[6]=v1.z; vals[7]=v1.w;
                vals[8]=v2.x; vals[9]=v2.y; vals[10]=v2.z; vals[11]=v2.w;
                vals[12]=v3.x; vals[13]=v3.y; vals[14]=v3.z; vals[15]=v3.w;
            }
        }
        if (!inb)
            #pragma unroll
            for (int i = 0; i < 16; ++i) vals[i] = 0.f;

        unsigned hiw[8];
        #pragma unroll
        for (int p = 0; p < 8; ++p) {
            __half2 hh = __floats2half2_rn(vals[2 * p], vals[2 * p + 1]);
            hiw[p] = *reinterpret_cast<unsigned*>(&hh);
        }
        const unsigned swb = (unsigned)((h & 4) << 2);   // 0 or 16
        char* hrow = smem + (size_t)h * 32;
        *(uint4*)(hrow + swb)        = make_uint4(hiw[0], hiw[1], hiw[2], hiw[3]);
        *(uint4*)(hrow + (swb ^ 16)) = make_uint4(hiw[4], hiw[5], hiw[6], hiw[7]);
    }
    __syncthreads();

    // ---- per-lane ldmatrix base rows (2 m16 groups per warp) ----
    const int w    = tid >> 5;
    const int lane = tid & 31;
    const unsigned sbase = smem_u32(smem);
    const unsigned s16 = (unsigned)((lane >> 4) << 4);   // which 16B k-half
    int hrow0[2];
    #pragma unroll
    for (int g = 0; g < 2; ++g) {
        const int v = w * 32 + g * 16 + (lane & 15);
        const int x = v & 7, y = (v >> 3) & 7, z = v >> 6;
        hrow0[g] = (x + 1) + 10 * (y + 1) + 100 * (z + 1);
    }

    float c[2][2][4];
    #pragma unroll
    for (int g = 0; g < 2; ++g)
        #pragma unroll
        for (int n = 0; n < 2; ++n)
            #pragma unroll
            for (int i = 0; i < 4; ++i) c[g][n][i] = 0.f;

    const uint4* sB = (const uint4*)(smem + B_OFF) + lane;

    #pragma unroll 1
    for (int tap = 0; tap < 27; ++tap) {
        const int toff = c_toff[tap];
        const uint4 bw = sB[tap * 32];        // both n8 fragments, one LDS.128
        #pragma unroll
        for (int g = 0; g < 2; ++g) {
            const int h1 = hrow0[g] + toff;
            const unsigned swb = (unsigned)((h1 & 4) << 2);
            const unsigned addr = sbase + (unsigned)(h1 * 32) + (s16 ^ swb);
            unsigned A0[4];
            ldsm_x4(A0, addr);
            mma_f16(c[g][0], A0, bw.x, bw.y);
            mma_f16(c[g][1], A0, bw.z, bw.w);
        }
    }

    // ---- epilogue: scatter C fragments + bias ----
    const int gid = lane >> 2;
    const int cp  = (lane & 3) * 2;
    const float2 bv0 = *(const float2*)(bias + l * 16 + cp);
    const float2 bv1 = *(const float2*)(bias + l * 16 + 8 + cp);
    float* outbase = out + (size_t)bb * N_TOTAL * 16;

    #pragma unroll
    for (int g = 0; g < 2; ++g) {
        #pragma unroll
        for (int rs = 0; rs < 2; ++rs) {
            const int v = w * 32 + g * 16 + gid + rs * 8;
            const int x = v & 7, y = (v >> 3) & 7, z = v >> 6;
            const int gx = x0 + x, gy = y0 + y, gz = z0 + z;
            if (gx < R && gy < R && gz < R) {
                float* o = outbase + (size_t)(off + gx + gy * R + gz * R * R) * 16;
                *(float2*)(o + cp) =
                    make_float2(c[g][0][rs * 2]     + bv0.x,
                                c[g][0][rs * 2 + 1] + bv0.y);
                *(float2*)(o + 8 + cp) =
                    make_float2(c[g][1][rs * 2]     + bv1.x,
                                c[g][1][rs * 2 + 1] + bv1.y);
            }
        }
    }
}

extern "C" void kernel_launch(void* const* d_in, const int* in_sizes, int n_in,
                              void* d_out, int out_size)
{
    const float* input  = (const float*)d_in[0];
    const float* weight = (const float*)d_in[1];
    const float* bias   = (const float*)d_in[2];
    float* out = (float*)d_out;

    prep_weights<<<54, 256>>>(weight);

    cudaFuncSetAttribute(conv3d_hmma3_kernel,
                         cudaFuncAttributeMaxDynamicSharedMemorySize, SMEM_BYTES);
    dim3 grid(N_TILES, 2);
    conv3d_hmma3_kernel<<<grid, 256, SMEM_BYTES>>>(input, bias, out);
}